// round 17
// baseline (speedup 1.0000x reference)
#include <cuda_runtime.h>
#include <cstdint>

#define BB 256
#define LL 500
#define EE 300
#define NROWS (BB * LL)          // 128000
#define NWV 18                   // 3 + 5 + 7 conv rows + 3 cw rows

// ---- dots kernel config ----
#define T1 128                   // 4 warps -> all 4 SMSPs
#define TROWS 128                // rows per block (each thread: 2 rows x 9 wv)
#define EK 60                    // e-chunk (300 = 5 * 60)
#define NCHUNK 5
#define XSTR 64                  // words per x-row in smem (32 x 8B slots, swizzled)
#define WSTR 300                 // words per w-row in smem (full width, staged once)

// 9.2 MB scratch for the 18 dot products per row
__device__ float g_Q[(size_t)NROWS * NWV];

__device__ __forceinline__ unsigned long long ffma2(unsigned long long a,
                                                    unsigned long long b,
                                                    unsigned long long c) {
    unsigned long long d;
    asm("fma.rn.f32x2 %0, %1, %2, %3;" : "=l"(d) : "l"(a), "l"(b), "l"(c));
    return d;
}

// ---------------------------------------------------------------------------
// Kernel 1: Q[row][0:18] = x[row] . W[wv]   (tall-skinny GEMM, f32x2 FMAs)
//   wv 0-2 : aw3 rows, 3-7 : aw5 rows, 8-14 : aw7 rows, 15/16/17 : cw3/5/7
// Warp w: cgrp = w&1 (wv 0-8 / 9-17), rgrp = w>>1. Thread handles rows
// r0 = rgrp*32+lane and r0+64.
// Software pipeline: chunk c+1's 15 LDG.128 are issued into registers at the
// top of chunk c; compute (~1600 cyc) hides the DRAM latency; STS after
// compute. W is staged to smem once per block.
// ---------------------------------------------------------------------------
__global__ __launch_bounds__(T1, 3) void dots_kernel(
    const float* __restrict__ x,
    const float* __restrict__ aw3, const float* __restrict__ aw5,
    const float* __restrict__ aw7,
    const float* __restrict__ cw3, const float* __restrict__ cw5,
    const float* __restrict__ cw7)
{
    __shared__ __align__(16) float xs[TROWS * XSTR];   // 32 KB, swizzled
    __shared__ __align__(16) float ws[NWV * WSTR];     // 21.6 KB

    const int tid  = threadIdx.x;
    const int lane = tid & 31;
    const int w    = tid >> 5;
    const int cgrp = w & 1;                    // wv group: 0 -> 0-8, 1 -> 9-17
    const int row0 = ((w >> 1) << 5) + lane;   // 0..63
    const size_t rowBase = (size_t)blockIdx.x * TROWS;
    const float* xbase = x + rowBase * EE;

    // staging map for this thread: t = tid + it*128 -> (row, quad)
    int srow[15], squad[15];
    #pragma unroll
    for (int it = 0; it < 15; it++) {
        int t = tid + it * T1;
        srow[it] = t / 15;
        squad[it] = t % 15;
    }

    unsigned long long acc[2][9];
    #pragma unroll
    for (int i = 0; i < 2; i++)
        #pragma unroll
        for (int c = 0; c < 9; c++) acc[i][c] = 0ull;

    // ---- stage W once: 18 rows x 300 floats (75 float4 each)
    for (int idx = tid; idx < NWV * 75; idx += T1) {
        int wr = idx / 75, q = idx % 75;
        const float* src;
        if (wr < 3)       src = aw3 + wr * EE;
        else if (wr < 8)  src = aw5 + (wr - 3) * EE;
        else if (wr < 15) src = aw7 + (wr - 8) * EE;
        else              src = (wr == 15) ? cw3 : (wr == 16) ? cw5 : cw7;
        *reinterpret_cast<float4*>(&ws[wr * WSTR + q * 4]) =
            *reinterpret_cast<const float4*>(src + q * 4);
    }

    // ---- prologue: prefetch + store chunk 0
    float4 pf[15];
    #pragma unroll
    for (int it = 0; it < 15; it++)
        pf[it] = *reinterpret_cast<const float4*>(
            xbase + (size_t)srow[it] * EE + squad[it] * 4);
    #pragma unroll
    for (int it = 0; it < 15; it++) {
        int rr = srow[it] & 15, q = squad[it];
        float2* b2 = reinterpret_cast<float2*>(&xs[srow[it] * XSTR]);
        b2[(2 * q) ^ rr]     = make_float2(pf[it].x, pf[it].y);
        b2[(2 * q + 1) ^ rr] = make_float2(pf[it].z, pf[it].w);
    }
    __syncthreads();

    #pragma unroll 1
    for (int ck = 0; ck < NCHUNK; ck++) {
        // prefetch chunk ck+1 into registers (hidden behind compute below)
        if (ck < NCHUNK - 1) {
            const int ce = (ck + 1) * EK;
            #pragma unroll
            for (int it = 0; it < 15; it++)
                pf[it] = *reinterpret_cast<const float4*>(
                    xbase + (size_t)srow[it] * EE + ce + squad[it] * 4);
        }

        // ---- compute chunk ck
        const int wof = cgrp * 9 * WSTR + ck * EK;
        #pragma unroll
        for (int e = 0; e < EK; e += 4) {
            unsigned long long wv0[9], wv1[9];
            #pragma unroll
            for (int c = 0; c < 9; c++) {
                ulonglong2 w2 = *reinterpret_cast<const ulonglong2*>(
                    &ws[wof + c * WSTR + e]);          // broadcast LDS.128
                wv0[c] = w2.x;
                wv1[c] = w2.y;
            }
            #pragma unroll
            for (int i = 0; i < 2; i++) {
                int row = row0 + 64 * i;
                const unsigned long long* xr =
                    reinterpret_cast<const unsigned long long*>(&xs[row * XSTR]);
                int rr = row & 15;
                unsigned long long xa = xr[(e / 2) ^ rr];
                unsigned long long xb = xr[(e / 2 + 1) ^ rr];
                #pragma unroll
                for (int c = 0; c < 9; c++) {
                    acc[i][c] = ffma2(xa, wv0[c], acc[i][c]);
                    acc[i][c] = ffma2(xb, wv1[c], acc[i][c]);
                }
            }
        }
        __syncthreads();                 // all warps done reading xs

        if (ck < NCHUNK - 1) {
            #pragma unroll
            for (int it = 0; it < 15; it++) {
                int rr = srow[it] & 15, q = squad[it];
                float2* b2 = reinterpret_cast<float2*>(&xs[srow[it] * XSTR]);
                b2[(2 * q) ^ rr]     = make_float2(pf[it].x, pf[it].y);
                b2[(2 * q + 1) ^ rr] = make_float2(pf[it].z, pf[it].w);
            }
            __syncthreads();             // xs ready for next chunk
        }
    }

    // ---- reduce f32x2 pairs, stage into smem (reuse xs), write coalesced
    #pragma unroll
    for (int i = 0; i < 2; i++) {
        int row = row0 + 64 * i;
        #pragma unroll
        for (int c = 0; c < 9; c++) {
            float lo, hi;
            asm("mov.b64 {%0,%1}, %2;" : "=f"(lo), "=f"(hi) : "l"(acc[i][c]));
            xs[row * NWV + cgrp * 9 + c] = lo + hi;
        }
    }
    __syncthreads();

    float* qdst = g_Q + rowBase * NWV;   // block's 128*18 region is contiguous
    #pragma unroll
    for (int t = tid; t < TROWS * NWV / 4; t += T1) {
        *reinterpret_cast<float4*>(qdst + t * 4) =
            *reinterpret_cast<const float4*>(&xs[t * 4]);
    }
}

// ---------------------------------------------------------------------------
// Kernel 2: shift-combine + activations (unchanged from best run)
// ---------------------------------------------------------------------------
__global__ void combine_kernel(
    const float* __restrict__ ab3, const float* __restrict__ cb3,
    const float* __restrict__ ab5, const float* __restrict__ cb5,
    const float* __restrict__ ab7, const float* __restrict__ cb7,
    float* __restrict__ out)
{
    int row = blockIdx.x * blockDim.x + threadIdx.x;
    if (row >= NROWS) return;
    int l = row % LL;
    const float* q = g_Q + (size_t)row * NWV;

    float s3 = 0.f, s5 = 0.f, s7 = 0.f;
    #pragma unroll
    for (int j = 0; j < 3; j++) {
        int d = j - 1, nl = l + d;
        if (nl >= 0 && nl < LL) s3 += q[(long)d * NWV + j];
    }
    #pragma unroll
    for (int j = 0; j < 5; j++) {
        int d = j - 2, nl = l + d;
        if (nl >= 0 && nl < LL) s5 += q[(long)d * NWV + 3 + j];
    }
    #pragma unroll
    for (int j = 0; j < 7; j++) {
        int d = j - 3, nl = l + d;
        if (nl >= 0 && nl < LL) s7 += q[(long)d * NWV + 8 + j];
    }

    float d3 = q[15], d5 = q[16], d7 = q[17];
    float sc3 = 1.f / (1.f + __expf(-(s3 + ab3[0])));
    float sc5 = 1.f / (1.f + __expf(-(s5 + ab5[0])));
    float sc7 = 1.f / (1.f + __expf(-(s7 + ab7[0])));

    out[row]             = tanhf(sc3 * d3 + cb3[0]);
    out[NROWS + row]     = tanhf(sc5 * d5 + cb5[0]);
    out[2 * NROWS + row] = tanhf(sc7 * d7 + cb7[0]);
}

// ---------------------------------------------------------------------------
extern "C" void kernel_launch(void* const* d_in, const int* in_sizes, int n_in,
                              void* d_out, int out_size) {
    const float* x   = (const float*)d_in[0];
    const float* aw3 = (const float*)d_in[1];
    const float* ab3 = (const float*)d_in[2];
    const float* cw3 = (const float*)d_in[3];
    const float* cb3 = (const float*)d_in[4];
    const float* aw5 = (const float*)d_in[5];
    const float* ab5 = (const float*)d_in[6];
    const float* cw5 = (const float*)d_in[7];
    const float* cb5 = (const float*)d_in[8];
    const float* aw7 = (const float*)d_in[9];
    const float* ab7 = (const float*)d_in[10];
    const float* cw7 = (const float*)d_in[11];
    const float* cb7 = (const float*)d_in[12];
    float* out = (float*)d_out;

    dots_kernel<<<NROWS / TROWS, T1>>>(x, aw3, aw5, aw7, cw3, cw5, cw7);
    combine_kernel<<<(NROWS + 255) / 256, 256>>>(ab3, cb3, ab5, cb5, ab7, cb7, out);
}